// round 12
// baseline (speedup 1.0000x reference)
#include <cuda_runtime.h>
#include <cstdint>

// RelationalModule via warp-level mma.sync m16n8k16 fp16 2-term split,
// two i's per loop unit for tensor-pipe overlap.
// Inputs: 0 x_img(64*1600) 1 W0(130*32) 2 b0 3 W1 4 b1 5 W2 6 b2 7 Wp 8 bp 9 Wo 10 bo
// Output: 32 f32.

#define N_PIX 1600
#define HID   32
#define NJT   (N_PIX / 32)          // 50 j-tiles
#define IP_PER_JT (N_PIX / 2)       // 800 2-i units per j-tile
#define NUNIT2 (NJT * IP_PER_JT)    // 40,000 2-i units
#define NCTA  296                   // 2 CTAs/SM
#define WPC   4
#define NW    (NCTA * WPC)          // 1184 warps

__device__ __align__(16) float g_a[N_PIX * HID];   // [n][k]
__device__ __align__(16) float g_b[N_PIX * HID];   // [n][k], includes +b0
__device__ __align__(16) float g_part[NW * HID];

// ---------------------------------------------------------------------------
// helpers
// ---------------------------------------------------------------------------
__device__ __forceinline__ void splitpairH(float x0, float x1,
                                           uint32_t& hi, uint32_t& lo) {
    uint32_t h;
    asm("cvt.rn.f16x2.f32 %0, %1, %2;" : "=r"(h) : "f"(x1), "f"(x0));
    float r0, r1;
    asm("{.reg .f16 lth, mth; mov.b32 {lth, mth}, %2;\n\t"
        "cvt.f32.f16 %0, lth; cvt.f32.f16 %1, mth;}"
        : "=f"(r0), "=f"(r1) : "r"(h));
    float d0 = x0 - r0, d1 = x1 - r1;
    uint32_t l;
    asm("cvt.rn.f16x2.f32 %0, %1, %2;" : "=r"(l) : "f"(d1), "f"(d0));
    hi = h; lo = l;
}
__device__ __forceinline__ uint32_t packH(float x0, float x1) {
    uint32_t h;
    asm("cvt.rn.f16x2.f32 %0, %1, %2;" : "=r"(h) : "f"(x1), "f"(x0));
    return h;
}
__device__ __forceinline__ void mma16816(float* d, const uint32_t* a,
                                         const uint32_t* b) {
    asm("mma.sync.aligned.m16n8k16.row.col.f32.f16.f16.f32 "
        "{%0,%1,%2,%3}, {%4,%5,%6,%7}, {%8,%9}, {%0,%1,%2,%3};"
        : "+f"(d[0]), "+f"(d[1]), "+f"(d[2]), "+f"(d[3])
        : "r"(a[0]), "r"(a[1]), "r"(a[2]), "r"(a[3]), "r"(b[0]), "r"(b[1]));
}

struct AFrag { uint32_t h[2][2][4]; uint32_t l[2][2][4]; };  // [mt][kbk][idx]

// build h0 = relu(a_j + b_i) and split to fp16 hi/lo fragments
__device__ __forceinline__ void build_h0(const float2 (&av)[2][2][2][2],
                                         const float2 (&bv)[4], AFrag& A) {
#pragma unroll
    for (int mt = 0; mt < 2; mt++)
#pragma unroll
        for (int kbk = 0; kbk < 2; kbk++)
#pragma unroll
            for (int half = 0; half < 2; half++) {
                float2 a0v = av[mt][kbk][half][0];
                float2 a1v = av[mt][kbk][half][1];
                float2 b = bv[kbk * 2 + half];
                float h00 = fmaxf(a0v.x + b.x, 0.f);
                float h01 = fmaxf(a0v.y + b.y, 0.f);
                float h10 = fmaxf(a1v.x + b.x, 0.f);
                float h11 = fmaxf(a1v.y + b.y, 0.f);
                splitpairH(h00, h01, A.h[mt][kbk][half * 2 + 0],
                                     A.l[mt][kbk][half * 2 + 0]);
                splitpairH(h10, h11, A.h[mt][kbk][half * 2 + 1],
                                     A.l[mt][kbk][half * 2 + 1]);
            }
}

// D = bias; D += Ah@W + Al@W  (2-term fp16)
__device__ __forceinline__ void layer(const AFrag& A,
                                      const uint32_t (&Bh)[2][4][2],
                                      const float (&bias)[8],
                                      float (&D)[2][4][4]) {
#pragma unroll
    for (int mt = 0; mt < 2; mt++)
#pragma unroll
        for (int nt = 0; nt < 4; nt++) {
            D[mt][nt][0] = bias[2 * nt]; D[mt][nt][1] = bias[2 * nt + 1];
            D[mt][nt][2] = bias[2 * nt]; D[mt][nt][3] = bias[2 * nt + 1];
        }
#pragma unroll
    for (int mt = 0; mt < 2; mt++)
#pragma unroll
        for (int nt = 0; nt < 4; nt++) {
            mma16816(D[mt][nt], A.h[mt][0], Bh[0][nt]);
            mma16816(D[mt][nt], A.h[mt][1], Bh[1][nt]);
            mma16816(D[mt][nt], A.l[mt][0], Bh[0][nt]);
            mma16816(D[mt][nt], A.l[mt][1], Bh[1][nt]);
        }
}

// A = split(relu(D))  (C->A fragment layout identity)
__device__ __forceinline__ void relu_split(const float (&D)[2][4][4], AFrag& A) {
#pragma unroll
    for (int mt = 0; mt < 2; mt++)
#pragma unroll
        for (int kbk = 0; kbk < 2; kbk++) {
            int n0 = 2 * kbk, n1 = 2 * kbk + 1;
            splitpairH(fmaxf(D[mt][n0][0], 0.f), fmaxf(D[mt][n0][1], 0.f),
                       A.h[mt][kbk][0], A.l[mt][kbk][0]);
            splitpairH(fmaxf(D[mt][n0][2], 0.f), fmaxf(D[mt][n0][3], 0.f),
                       A.h[mt][kbk][1], A.l[mt][kbk][1]);
            splitpairH(fmaxf(D[mt][n1][0], 0.f), fmaxf(D[mt][n1][1], 0.f),
                       A.h[mt][kbk][2], A.l[mt][kbk][2]);
            splitpairH(fmaxf(D[mt][n1][2], 0.f), fmaxf(D[mt][n1][3], 0.f),
                       A.h[mt][kbk][3], A.l[mt][kbk][3]);
        }
}

// ---------------------------------------------------------------------------
// Phase 0: per-pixel embeddings, 4-way channel split.
// ---------------------------------------------------------------------------
__global__ void precompute_ab(const float* __restrict__ x,
                              const float* __restrict__ W0,
                              const float* __restrict__ b0) {
    int t = blockIdx.x * blockDim.x + threadIdx.x;
    if (t >= N_PIX * HID * 4) return;
    int c = t & 3;
    int k = (t >> 2) & 31;
    int n = t >> 7;
    float fa = 0.f, fb = 0.f;
    int ch0 = c * 16;
#pragma unroll
    for (int q = 0; q < 16; q++) {
        int ch = ch0 + q;
        float xv = x[ch * N_PIX + n];
        fa = fmaf(xv, W0[ch * HID + k], fa);
        fb = fmaf(xv, W0[(65 + ch) * HID + k], fb);
    }
    if (c == 0) {
        float cf = (float)n;
        fa = fmaf(cf, W0[64 * HID + k], fa);
        fb = fmaf(cf, W0[129 * HID + k], fb);
    }
    fa += __shfl_xor_sync(0xffffffffu, fa, 1);
    fa += __shfl_xor_sync(0xffffffffu, fa, 2);
    fb += __shfl_xor_sync(0xffffffffu, fb, 1);
    fb += __shfl_xor_sync(0xffffffffu, fb, 2);
    if (c == 0) {
        g_a[n * HID + k] = fa;
        g_b[n * HID + k] = fb + b0[k];
    }
}

// ---------------------------------------------------------------------------
// Phase 1: pair MLP, 2-i units. While i0 is in its scalar split phase,
// i1's MMAs fill the tensor pipe (plus cross-warp overlap).
// ---------------------------------------------------------------------------
__global__ void __launch_bounds__(128)
pair_kernel(const float* __restrict__ W1, const float* __restrict__ b1,
            const float* __restrict__ W2, const float* __restrict__ b2) {
    int lane = threadIdx.x & 31;
    int warp = threadIdx.x >> 5;
    int g = lane >> 2;              // 0..7
    int t = lane & 3;               // 0..3
    int w = blockIdx.x * WPC + warp;

    // ---- B fragments (fp16-rounded weights) ----
    uint32_t B1h[2][4][2], B2h[2][4][2];
#pragma unroll
    for (int kbk = 0; kbk < 2; kbk++)
#pragma unroll
        for (int nt = 0; nt < 4; nt++)
#pragma unroll
            for (int r = 0; r < 2; r++) {
                int n = 8 * nt + g;
                int k0 = kbk * 16 + r * 8 + 2 * t;
                B1h[kbk][nt][r] = packH(W1[k0 * HID + n], W1[(k0 + 1) * HID + n]);
                B2h[kbk][nt][r] = packH(W2[k0 * HID + n], W2[(k0 + 1) * HID + n]);
            }
    float bias1[8], bias2[8];
#pragma unroll
    for (int nt = 0; nt < 4; nt++) {
        bias1[2 * nt + 0] = b1[8 * nt + 2 * t];
        bias1[2 * nt + 1] = b1[8 * nt + 2 * t + 1];
        bias2[2 * nt + 0] = b2[8 * nt + 2 * t];
        bias2[2 * nt + 1] = b2[8 * nt + 2 * t + 1];
    }

    float accE[4], accO[4];
#pragma unroll
    for (int nt = 0; nt < 4; nt++) { accE[nt] = 0.f; accO[nt] = 0.f; }

    const float2* ga2 = (const float2*)g_a;
    const float2* gb2 = (const float2*)g_b;

    int u0 = (int)(((long long)w * NUNIT2) / NW);
    int u1 = (int)(((long long)(w + 1) * NUNIT2) / NW);
    int jt = u0 / IP_PER_JT;
    int ip = u0 - jt * IP_PER_JT;

    for (int u = u0; u < u1; u++) {
        int j0 = jt * 32;
        int i0 = ip * 2;

        // ---- per-unit loads: shared a-rows + both b-rows ----
        float2 av[2][2][2][2];   // [mt][kbk][half][row]
#pragma unroll
        for (int mt = 0; mt < 2; mt++) {
            int ra = j0 + mt * 16 + g;
#pragma unroll
            for (int kbk = 0; kbk < 2; kbk++)
#pragma unroll
                for (int half = 0; half < 2; half++) {
                    int fidx = kbk * 8 + half * 4 + t;
                    av[mt][kbk][half][0] = ga2[ra * 16 + fidx];
                    av[mt][kbk][half][1] = ga2[(ra + 8) * 16 + fidx];
                }
        }
        float2 bv0[4], bv1[4];
#pragma unroll
        for (int kk = 0; kk < 4; kk++) {
            bv0[kk] = gb2[i0 * 16 + kk * 4 + t];
            bv1[kk] = gb2[(i0 + 1) * 16 + kk * 4 + t];
        }

        // ---- dual-unit pipeline ----
        AFrag A0, A1;
        build_h0(av, bv0, A0);
        build_h0(av, bv1, A1);

        float D0[2][4][4], D1[2][4][4];
        layer(A0, B1h, bias1, D0);
        layer(A1, B1h, bias1, D1);

        relu_split(D0, A0);
        layer(A0, B2h, bias2, D0);

        relu_split(D1, A1);
        layer(A1, B2h, bias2, D1);

#pragma unroll
        for (int nt = 0; nt < 4; nt++) {
            accE[nt] += fmaxf(D0[0][nt][0], 0.f) + fmaxf(D0[0][nt][2], 0.f)
                      + fmaxf(D0[1][nt][0], 0.f) + fmaxf(D0[1][nt][2], 0.f)
                      + fmaxf(D1[0][nt][0], 0.f) + fmaxf(D1[0][nt][2], 0.f)
                      + fmaxf(D1[1][nt][0], 0.f) + fmaxf(D1[1][nt][2], 0.f);
            accO[nt] += fmaxf(D0[0][nt][1], 0.f) + fmaxf(D0[0][nt][3], 0.f)
                      + fmaxf(D0[1][nt][1], 0.f) + fmaxf(D0[1][nt][3], 0.f)
                      + fmaxf(D1[0][nt][1], 0.f) + fmaxf(D1[0][nt][3], 0.f)
                      + fmaxf(D1[1][nt][1], 0.f) + fmaxf(D1[1][nt][3], 0.f);
        }

        if (++ip == IP_PER_JT) { ip = 0; jt++; }
    }

    // ---- reduce over the 8 g-groups (t fixed) ----
#pragma unroll
    for (int nt = 0; nt < 4; nt++) {
#pragma unroll
        for (int o = 4; o < 32; o <<= 1) {
            accE[nt] += __shfl_xor_sync(0xffffffffu, accE[nt], o);
            accO[nt] += __shfl_xor_sync(0xffffffffu, accO[nt], o);
        }
    }
    if (lane < 4) {
#pragma unroll
        for (int nt = 0; nt < 4; nt++) {
            g_part[w * HID + 8 * nt + 2 * lane + 0] = accE[nt];
            g_part[w * HID + 8 * nt + 2 * lane + 1] = accO[nt];
        }
    }
}

// ---------------------------------------------------------------------------
// Phase 2: reduce 1184 partials -> s[32]; head MLP -> out[32]
// ---------------------------------------------------------------------------
__global__ void reduce_out(const float* __restrict__ Wp, const float* __restrict__ bp,
                           const float* __restrict__ Wo, const float* __restrict__ bo,
                           float* __restrict__ out) {
    __shared__ float tmp[8][HID];
    __shared__ float s[HID], pvec[HID];
    int tid = threadIdx.x;              // 256
    int k = tid & 31, grp = tid >> 5;
    float lsum = 0.f;
    for (int b = grp; b < NW; b += 8)
        lsum += g_part[b * HID + k];
    tmp[grp][k] = lsum;
    __syncthreads();
    if (tid < HID) {
        float t = 0.f;
#pragma unroll
        for (int gg = 0; gg < 8; gg++) t += tmp[gg][tid];
        s[tid] = t;
    }
    __syncthreads();
    if (tid < HID) {
        float t = bp[tid];
#pragma unroll
        for (int kk = 0; kk < HID; kk++) t = fmaf(s[kk], Wp[kk * HID + tid], t);
        pvec[tid] = fmaxf(t, 0.f);
    }
    __syncthreads();
    if (tid < HID) {
        float t = bo[tid];
#pragma unroll
        for (int kk = 0; kk < HID; kk++) t = fmaf(pvec[kk], Wo[kk * HID + tid], t);
        out[tid] = t;
    }
}

// ---------------------------------------------------------------------------
extern "C" void kernel_launch(void* const* d_in, const int* in_sizes, int n_in,
                              void* d_out, int out_size) {
    const float* x  = (const float*)d_in[0];
    const float* W0 = (const float*)d_in[1];
    const float* b0 = (const float*)d_in[2];
    const float* W1 = (const float*)d_in[3];
    const float* b1 = (const float*)d_in[4];
    const float* W2 = (const float*)d_in[5];
    const float* b2 = (const float*)d_in[6];
    const float* Wp = (const float*)d_in[7];
    const float* bp = (const float*)d_in[8];
    const float* Wo = (const float*)d_in[9];
    const float* bo = (const float*)d_in[10];
    float* out = (float*)d_out;

    precompute_ab<<<(N_PIX * HID * 4 + 255) / 256, 256>>>(x, W0, b0);
    pair_kernel<<<NCTA, 128>>>(W1, b1, W2, b2);
    reduce_out<<<1, 256>>>(Wp, bp, Wo, bo, out);
}

// round 13
// speedup vs baseline: 1.7302x; 1.7302x over previous
#include <cuda_runtime.h>
#include <cstdint>

// RelationalModule via warp-level mma.sync m16n8k16 plain fp16 (1-term),
// bias folded into the MMA C operand.
// Inputs: 0 x_img(64*1600) 1 W0(130*32) 2 b0 3 W1 4 b1 5 W2 6 b2 7 Wp 8 bp 9 Wo 10 bo
// Output: 32 f32.

#define N_PIX 1600
#define HID   32
#define NJT   (N_PIX / 32)          // 50 j-tiles
#define NUNIT (NJT * N_PIX)         // 80,000 units (1 i x 32 j each)
#define NCTA  296                   // 2 CTAs/SM (proven config)
#define WPC   4
#define NW    (NCTA * WPC)          // 1184 warps

__device__ __align__(16) float g_a[N_PIX * HID];   // [n][k]
__device__ __align__(16) float g_b[N_PIX * HID];   // [n][k], includes +b0
__device__ __align__(16) float g_part[NW * HID];

// ---------------------------------------------------------------------------
// helpers
// ---------------------------------------------------------------------------
__device__ __forceinline__ uint32_t packH(float x0, float x1) {
    uint32_t h;
    asm("cvt.rn.f16x2.f32 %0, %1, %2;" : "=r"(h) : "f"(x1), "f"(x0));
    return h;
}
// d = a*b + d (accumulate in place)
__device__ __forceinline__ void mma16816(float* d, const uint32_t* a,
                                         const uint32_t* b) {
    asm("mma.sync.aligned.m16n8k16.row.col.f32.f16.f16.f32 "
        "{%0,%1,%2,%3}, {%4,%5,%6,%7}, {%8,%9}, {%0,%1,%2,%3};"
        : "+f"(d[0]), "+f"(d[1]), "+f"(d[2]), "+f"(d[3])
        : "r"(a[0]), "r"(a[1]), "r"(a[2]), "r"(a[3]), "r"(b[0]), "r"(b[1]));
}
// d = a*b + {c0,c1,c0,c1}  (bias as C operand; kills the D-init MOVs)
__device__ __forceinline__ void mma16816_c(float* d, const uint32_t* a,
                                           const uint32_t* b,
                                           float c0, float c1) {
    asm("mma.sync.aligned.m16n8k16.row.col.f32.f16.f16.f32 "
        "{%0,%1,%2,%3}, {%4,%5,%6,%7}, {%8,%9}, {%10,%11,%10,%11};"
        : "=f"(d[0]), "=f"(d[1]), "=f"(d[2]), "=f"(d[3])
        : "r"(a[0]), "r"(a[1]), "r"(a[2]), "r"(a[3]), "r"(b[0]), "r"(b[1]),
          "f"(c0), "f"(c1));
}

// ---------------------------------------------------------------------------
// Phase 0: per-pixel embeddings, 4-way channel split.
// ---------------------------------------------------------------------------
__global__ void precompute_ab(const float* __restrict__ x,
                              const float* __restrict__ W0,
                              const float* __restrict__ b0) {
    int t = blockIdx.x * blockDim.x + threadIdx.x;
    if (t >= N_PIX * HID * 4) return;
    int c = t & 3;
    int k = (t >> 2) & 31;
    int n = t >> 7;
    float fa = 0.f, fb = 0.f;
    int ch0 = c * 16;
#pragma unroll
    for (int q = 0; q < 16; q++) {
        int ch = ch0 + q;
        float xv = x[ch * N_PIX + n];
        fa = fmaf(xv, W0[ch * HID + k], fa);
        fb = fmaf(xv, W0[(65 + ch) * HID + k], fb);
    }
    if (c == 0) {
        float cf = (float)n;
        fa = fmaf(cf, W0[64 * HID + k], fa);
        fb = fmaf(cf, W0[129 * HID + k], fb);
    }
    fa += __shfl_xor_sync(0xffffffffu, fa, 1);
    fa += __shfl_xor_sync(0xffffffffu, fa, 2);
    fb += __shfl_xor_sync(0xffffffffu, fb, 1);
    fb += __shfl_xor_sync(0xffffffffu, fb, 2);
    if (c == 0) {
        g_a[n * HID + k] = fa;
        g_b[n * HID + k] = fb + b0[k];
    }
}

// ---------------------------------------------------------------------------
// Phase 1: pair MLP, plain fp16 MMA. 32 MMAs/unit, ~190 scalar issues/unit.
// a-rows hoisted per j-tile segment; bv prefetched one iter ahead.
// ---------------------------------------------------------------------------
__global__ void __launch_bounds__(128)
pair_kernel(const float* __restrict__ W1, const float* __restrict__ b1,
            const float* __restrict__ W2, const float* __restrict__ b2) {
    int lane = threadIdx.x & 31;
    int warp = threadIdx.x >> 5;
    int g = lane >> 2;              // 0..7
    int t = lane & 3;               // 0..3
    int w = blockIdx.x * WPC + warp;

    // ---- B fragments (fp16-rounded weights, both layers) ----
    uint32_t B1h[2][4][2], B2h[2][4][2];
#pragma unroll
    for (int kbk = 0; kbk < 2; kbk++)
#pragma unroll
        for (int nt = 0; nt < 4; nt++)
#pragma unroll
            for (int r = 0; r < 2; r++) {
                int n = 8 * nt + g;
                int k0 = kbk * 16 + r * 8 + 2 * t;
                B1h[kbk][nt][r] = packH(W1[k0 * HID + n], W1[(k0 + 1) * HID + n]);
                B2h[kbk][nt][r] = packH(W2[k0 * HID + n], W2[(k0 + 1) * HID + n]);
            }
    float bias1[8], bias2[8];
#pragma unroll
    for (int nt = 0; nt < 4; nt++) {
        bias1[2 * nt + 0] = b1[8 * nt + 2 * t];
        bias1[2 * nt + 1] = b1[8 * nt + 2 * t + 1];
        bias2[2 * nt + 0] = b2[8 * nt + 2 * t];
        bias2[2 * nt + 1] = b2[8 * nt + 2 * t + 1];
    }

    float accE[4], accO[4];
#pragma unroll
    for (int nt = 0; nt < 4; nt++) { accE[nt] = 0.f; accO[nt] = 0.f; }

    const float2* ga2 = (const float2*)g_a;
    const float2* gb2 = (const float2*)g_b;

    int u0 = (int)(((long long)w * NUNIT) / NW);
    int u1 = (int)(((long long)(w + 1) * NUNIT) / NW);
    int u  = u0;
    int jt = u0 / N_PIX;
    int i  = u0 - jt * N_PIX;

    while (u < u1) {
        int segEnd = (jt + 1) * N_PIX;
        if (segEnd > u1) segEnd = u1;
        int j0 = jt * 32;

        // ---- hoisted a-rows for this j-tile ----
        float2 av[2][2][2][2];   // [mt][kbk][half][row]
#pragma unroll
        for (int mt = 0; mt < 2; mt++) {
            int ra = j0 + mt * 16 + g;
#pragma unroll
            for (int kbk = 0; kbk < 2; kbk++)
#pragma unroll
                for (int half = 0; half < 2; half++) {
                    int fidx = kbk * 8 + half * 4 + t;
                    av[mt][kbk][half][0] = ga2[ra * 16 + fidx];
                    av[mt][kbk][half][1] = ga2[(ra + 8) * 16 + fidx];
                }
        }

        // prefetch first bv of segment
        float2 bvp[4];
#pragma unroll
        for (int kk = 0; kk < 4; kk++)
            bvp[kk] = gb2[i * 16 + kk * 4 + t];

        for (; u < segEnd; ) {
            float2 bvc[4];
#pragma unroll
            for (int kk = 0; kk < 4; kk++) bvc[kk] = bvp[kk];
            u++;
            int inext = (u < segEnd) ? (i + 1) : i;
#pragma unroll
            for (int kk = 0; kk < 4; kk++)
                bvp[kk] = gb2[inext * 16 + kk * 4 + t];

            // ---- h0 A-fragments: relu(a+b) packed to fp16 (1-term) ----
            uint32_t A[2][2][4];
#pragma unroll
            for (int mt = 0; mt < 2; mt++)
#pragma unroll
                for (int kbk = 0; kbk < 2; kbk++)
#pragma unroll
                    for (int half = 0; half < 2; half++) {
                        float2 a0v = av[mt][kbk][half][0];
                        float2 a1v = av[mt][kbk][half][1];
                        float2 b = bvc[kbk * 2 + half];
                        float h00 = fmaxf(a0v.x + b.x, 0.f);
                        float h01 = fmaxf(a0v.y + b.y, 0.f);
                        float h10 = fmaxf(a1v.x + b.x, 0.f);
                        float h11 = fmaxf(a1v.y + b.y, 0.f);
                        A[mt][kbk][half * 2 + 0] = packH(h00, h01);
                        A[mt][kbk][half * 2 + 1] = packH(h10, h11);
                    }

            // ---- layer 1: D = A@W1 + b1 (bias via C operand) ----
            float D[2][4][4];
#pragma unroll
            for (int mt = 0; mt < 2; mt++)
#pragma unroll
                for (int nt = 0; nt < 4; nt++) {
                    mma16816_c(D[mt][nt], A[mt][0], B1h[0][nt],
                               bias1[2 * nt], bias1[2 * nt + 1]);
                    mma16816(D[mt][nt], A[mt][1], B1h[1][nt]);
                }

            // ---- h1 = relu(D1) packed (C->A layout identity) ----
#pragma unroll
            for (int mt = 0; mt < 2; mt++)
#pragma unroll
                for (int kbk = 0; kbk < 2; kbk++) {
                    int n0 = 2 * kbk, n1 = 2 * kbk + 1;
                    A[mt][kbk][0] = packH(fmaxf(D[mt][n0][0], 0.f),
                                          fmaxf(D[mt][n0][1], 0.f));
                    A[mt][kbk][1] = packH(fmaxf(D[mt][n0][2], 0.f),
                                          fmaxf(D[mt][n0][3], 0.f));
                    A[mt][kbk][2] = packH(fmaxf(D[mt][n1][0], 0.f),
                                          fmaxf(D[mt][n1][1], 0.f));
                    A[mt][kbk][3] = packH(fmaxf(D[mt][n1][2], 0.f),
                                          fmaxf(D[mt][n1][3], 0.f));
                }

            // ---- layer 2: D = A@W2 + b2 ----
#pragma unroll
            for (int mt = 0; mt < 2; mt++)
#pragma unroll
                for (int nt = 0; nt < 4; nt++) {
                    mma16816_c(D[mt][nt], A[mt][0], B2h[0][nt],
                               bias2[2 * nt], bias2[2 * nt + 1]);
                    mma16816(D[mt][nt], A[mt][1], B2h[1][nt]);
                }

            // ---- acc += relu(D2), rows folded ----
#pragma unroll
            for (int nt = 0; nt < 4; nt++) {
                accE[nt] += fmaxf(D[0][nt][0], 0.f) + fmaxf(D[0][nt][2], 0.f)
                          + fmaxf(D[1][nt][0], 0.f) + fmaxf(D[1][nt][2], 0.f);
                accO[nt] += fmaxf(D[0][nt][1], 0.f) + fmaxf(D[0][nt][3], 0.f)
                          + fmaxf(D[1][nt][1], 0.f) + fmaxf(D[1][nt][3], 0.f);
            }

            i++;
        }
        if (u < u1) { jt++; i = 0; }
    }

    // ---- reduce over the 8 g-groups (t fixed) ----
#pragma unroll
    for (int nt = 0; nt < 4; nt++) {
#pragma unroll
        for (int o = 4; o < 32; o <<= 1) {
            accE[nt] += __shfl_xor_sync(0xffffffffu, accE[nt], o);
            accO[nt] += __shfl_xor_sync(0xffffffffu, accO[nt], o);
        }
    }
    if (lane < 4) {
#pragma unroll
        for (int nt = 0; nt < 4; nt++) {
            g_part[w * HID + 8 * nt + 2 * lane + 0] = accE[nt];
            g_part[w * HID + 8 * nt + 2 * lane + 1] = accO[nt];
        }
    }
}

// ---------------------------------------------------------------------------
// Phase 2: reduce 1184 partials -> s[32]; head MLP -> out[32]
// ---------------------------------------------------------------------------
__global__ void reduce_out(const float* __restrict__ Wp, const float* __restrict__ bp,
                           const float* __restrict__ Wo, const float* __restrict__ bo,
                           float* __restrict__ out) {
    __shared__ float tmp[8][HID];
    __shared__ float s[HID], pvec[HID];
    int tid = threadIdx.x;              // 256
    int k = tid & 31, grp = tid >> 5;
    float lsum = 0.f;
    for (int b = grp; b < NW; b += 8)
        lsum += g_part[b * HID + k];
    tmp[grp][k] = lsum;
    __syncthreads();
    if (tid < HID) {
        float t = 0.f;
#pragma unroll
        for (int gg = 0; gg < 8; gg++) t += tmp[gg][tid];
        s[tid] = t;
    }
    __syncthreads();
    if (tid < HID) {
        float t = bp[tid];
#pragma unroll
        for (int kk = 0; kk < HID; kk++) t = fmaf(s[kk], Wp[kk * HID + tid], t);
        pvec[tid] = fmaxf(t, 0.f);
    }
    __syncthreads();
    if (tid < HID) {
        float t = bo[tid];
#pragma unroll
        for (int kk = 0; kk < HID; kk++) t = fmaf(pvec[kk], Wo[kk * HID + tid], t);
        out[tid] = t;
    }
}

// ---------------------------------------------------------------------------
extern "C" void kernel_launch(void* const* d_in, const int* in_sizes, int n_in,
                              void* d_out, int out_size) {
    const float* x  = (const float*)d_in[0];
    const float* W0 = (const float*)d_in[1];
    const float* b0 = (const float*)d_in[2];
    const float* W1 = (const float*)d_in[3];
    const float* b1 = (const float*)d_in[4];
    const float* W2 = (const float*)d_in[5];
    const float* b2 = (const float*)d_in[6];
    const float* Wp = (const float*)d_in[7];
    const float* bp = (const float*)d_in[8];
    const float* Wo = (const float*)d_in[9];
    const float* bo = (const float*)d_in[10];
    float* out = (float*)d_out;

    precompute_ab<<<(N_PIX * HID * 4 + 255) / 256, 256>>>(x, W0, b0);
    pair_kernel<<<NCTA, 128>>>(W1, b1, W2, b2);
    reduce_out<<<1, 256>>>(Wp, bp, Wo, bo, out);
}

// round 14
// speedup vs baseline: 1.9733x; 1.1405x over previous
#include <cuda_runtime.h>
#include <cstdint>

// RelationalModule, full-fp16 datapath: packed-permuted f16 embeddings,
// m16n8k16 f16 C/D MMAs, HADD2/HMAX2 activation math.
// Inputs: 0 x_img(64*1600) 1 W0(130*32) 2 b0 3 W1 4 b1 5 W2 6 b2 7 Wp 8 bp 9 Wo 10 bo
// Output: 32 f32.

#define N_PIX 1600
#define HID   32
#define NJT   (N_PIX / 32)          // 50 j-tiles
#define NUNIT (NJT * N_PIX)         // 80,000 units (1 i x 32 j each)
#define NCTA  296                   // 2 CTAs/SM
#define WPC   4
#define NW    (NCTA * WPC)          // 1184 warps

// packed f16, permuted so thread t's 4 words per row are uint4 #t:
// word w = t*4+q holds k-pair (q&1)*8 + (q>>1)*16 + 2t (lo), +1 (hi)
__device__ __align__(16) unsigned short g_ah[N_PIX * HID];
__device__ __align__(16) unsigned short g_bh[N_PIX * HID];   // includes +b0
__device__ __align__(16) float g_part[NW * HID];

// ---------------------------------------------------------------------------
// helpers
// ---------------------------------------------------------------------------
__device__ __forceinline__ uint32_t hadd2(uint32_t a, uint32_t b) {
    uint32_t d; asm("add.f16x2 %0,%1,%2;" : "=r"(d) : "r"(a), "r"(b)); return d;
}
__device__ __forceinline__ uint32_t hrelu2(uint32_t a) {
    uint32_t d; asm("max.f16x2 %0,%1,%2;" : "=r"(d) : "r"(a), "r"(0u)); return d;
}
__device__ __forceinline__ uint32_t packH(float x0, float x1) {
    uint32_t h;
    asm("cvt.rn.f16x2.f32 %0, %1, %2;" : "=r"(h) : "f"(x1), "f"(x0));
    return h;
}
__device__ __forceinline__ void unpackH(uint32_t v, float& lo, float& hi) {
    asm("{.reg .f16 l,h; mov.b32 {l,h}, %2; cvt.f32.f16 %0, l; cvt.f32.f16 %1, h;}"
        : "=f"(lo), "=f"(hi) : "r"(v));
}
// f16 C/D mma: {d0,d1} = A@B + {c0,c1}
__device__ __forceinline__ void mmaH(uint32_t& d0, uint32_t& d1,
                                     const uint32_t* a, const uint32_t* b,
                                     uint32_t c0, uint32_t c1) {
    asm("mma.sync.aligned.m16n8k16.row.col.f16.f16.f16.f16 "
        "{%0,%1}, {%2,%3,%4,%5}, {%6,%7}, {%8,%9};"
        : "=r"(d0), "=r"(d1)
        : "r"(a[0]), "r"(a[1]), "r"(a[2]), "r"(a[3]), "r"(b[0]), "r"(b[1]),
          "r"(c0), "r"(c1));
}

// ---------------------------------------------------------------------------
// Phase 0: per-pixel embeddings -> permuted packed f16.
// 4-way channel split per (n,k) as before; c==0 lane writes one u16.
// ---------------------------------------------------------------------------
__global__ void precompute_ab(const float* __restrict__ x,
                              const float* __restrict__ W0,
                              const float* __restrict__ b0) {
    int t = blockIdx.x * blockDim.x + threadIdx.x;
    if (t >= N_PIX * HID * 4) return;
    int c = t & 3;
    int k = (t >> 2) & 31;
    int n = t >> 7;
    float fa = 0.f, fb = 0.f;
    int ch0 = c * 16;
#pragma unroll
    for (int q = 0; q < 16; q++) {
        int ch = ch0 + q;
        float xv = x[ch * N_PIX + n];
        fa = fmaf(xv, W0[ch * HID + k], fa);
        fb = fmaf(xv, W0[(65 + ch) * HID + k], fb);
    }
    if (c == 0) {
        float cf = (float)n;
        fa = fmaf(cf, W0[64 * HID + k], fa);
        fb = fmaf(cf, W0[129 * HID + k], fb);
    }
    fa += __shfl_xor_sync(0xffffffffu, fa, 1);
    fa += __shfl_xor_sync(0xffffffffu, fa, 2);
    fb += __shfl_xor_sync(0xffffffffu, fb, 1);
    fb += __shfl_xor_sync(0xffffffffu, fb, 2);
    if (c == 0) {
        int p = k >> 1;
        int pos = ((p & 3) * 4 + (p >> 2)) * 2 + (k & 1);
        unsigned short ha, hb;
        asm("cvt.rn.f16.f32 %0, %1;" : "=h"(ha) : "f"(fa));
        float fbb = fb + b0[k];
        asm("cvt.rn.f16.f32 %0, %1;" : "=h"(hb) : "f"(fbb));
        g_ah[n * HID + pos] = ha;
        g_bh[n * HID + pos] = hb;
    }
}

// ---------------------------------------------------------------------------
// Phase 1: pair MLP, f16 end-to-end. 32 MMAs/unit, ~105 scalar issues/unit.
// ---------------------------------------------------------------------------
__global__ void __launch_bounds__(128)
pair_kernel(const float* __restrict__ W1, const float* __restrict__ b1,
            const float* __restrict__ W2, const float* __restrict__ b2) {
    int lane = threadIdx.x & 31;
    int warp = threadIdx.x >> 5;
    int g = lane >> 2;              // 0..7
    int t = lane & 3;               // 0..3
    int w = blockIdx.x * WPC + warp;

    // ---- B fragments (fp16 weights, both layers) ----
    uint32_t B1h[2][4][2], B2h[2][4][2];
#pragma unroll
    for (int kbk = 0; kbk < 2; kbk++)
#pragma unroll
        for (int nt = 0; nt < 4; nt++)
#pragma unroll
            for (int r = 0; r < 2; r++) {
                int n = 8 * nt + g;
                int k0 = kbk * 16 + r * 8 + 2 * t;
                B1h[kbk][nt][r] = packH(W1[k0 * HID + n], W1[(k0 + 1) * HID + n]);
                B2h[kbk][nt][r] = packH(W2[k0 * HID + n], W2[(k0 + 1) * HID + n]);
            }
    // biases packed f16x2 at this lane's cols (2t, 2t+1) per nt
    uint32_t bias1p[4], bias2p[4];
#pragma unroll
    for (int nt = 0; nt < 4; nt++) {
        bias1p[nt] = packH(b1[8 * nt + 2 * t], b1[8 * nt + 2 * t + 1]);
        bias2p[nt] = packH(b2[8 * nt + 2 * t], b2[8 * nt + 2 * t + 1]);
    }

    float accE[4], accO[4];
#pragma unroll
    for (int nt = 0; nt < 4; nt++) { accE[nt] = 0.f; accO[nt] = 0.f; }

    const uint4* ga4 = (const uint4*)g_ah;   // 4 uint4 per row
    const uint4* gb4 = (const uint4*)g_bh;

    int u0 = (int)(((long long)w * NUNIT) / NW);
    int u1 = (int)(((long long)(w + 1) * NUNIT) / NW);
    int u  = u0;
    int jt = u0 / N_PIX;
    int i  = u0 - jt * N_PIX;

    while (u < u1) {
        int segEnd = (jt + 1) * N_PIX;
        if (segEnd > u1) segEnd = u1;
        int j0 = jt * 32;

        // ---- hoisted a-rows (packed): [mt][row] one uint4 each ----
        uint4 av[2][2];
#pragma unroll
        for (int mt = 0; mt < 2; mt++) {
            int ra = j0 + mt * 16 + g;
            av[mt][0] = ga4[ra * 4 + t];
            av[mt][1] = ga4[(ra + 8) * 4 + t];
        }

        uint4 bvp = gb4[i * 4 + t];   // prefetch

        for (; u < segEnd; ) {
            uint4 bv = bvp;
            u++;
            int inext = (u < segEnd) ? (i + 1) : i;
            bvp = gb4[inext * 4 + t];

            // ---- h0 = relu(a+b), already fragment-ordered ----
            // A[mt][kbk]: {row g q=2kbk, row g+8 q=2kbk, row g q=2kbk+1, row g+8 q=2kbk+1}
            uint32_t A[2][2][4];
#pragma unroll
            for (int mt = 0; mt < 2; mt++) {
                A[mt][0][0] = hrelu2(hadd2(av[mt][0].x, bv.x));
                A[mt][0][1] = hrelu2(hadd2(av[mt][1].x, bv.x));
                A[mt][0][2] = hrelu2(hadd2(av[mt][0].y, bv.y));
                A[mt][0][3] = hrelu2(hadd2(av[mt][1].y, bv.y));
                A[mt][1][0] = hrelu2(hadd2(av[mt][0].z, bv.z));
                A[mt][1][1] = hrelu2(hadd2(av[mt][1].z, bv.z));
                A[mt][1][2] = hrelu2(hadd2(av[mt][0].w, bv.w));
                A[mt][1][3] = hrelu2(hadd2(av[mt][1].w, bv.w));
            }

            // ---- layer 1 (f16 D), bias via C ----
            uint32_t D[2][4][2];
#pragma unroll
            for (int mt = 0; mt < 2; mt++)
#pragma unroll
                for (int nt = 0; nt < 4; nt++) {
                    mmaH(D[mt][nt][0], D[mt][nt][1], A[mt][0], B1h[0][nt],
                         bias1p[nt], bias1p[nt]);
                    mmaH(D[mt][nt][0], D[mt][nt][1], A[mt][1], B1h[1][nt],
                         D[mt][nt][0], D[mt][nt][1]);
                }

            // ---- h1 = relu(D): HMAX2 + register renaming (C->A identity) ----
#pragma unroll
            for (int mt = 0; mt < 2; mt++) {
                A[mt][0][0] = hrelu2(D[mt][0][0]);
                A[mt][0][1] = hrelu2(D[mt][0][1]);
                A[mt][0][2] = hrelu2(D[mt][1][0]);
                A[mt][0][3] = hrelu2(D[mt][1][1]);
                A[mt][1][0] = hrelu2(D[mt][2][0]);
                A[mt][1][1] = hrelu2(D[mt][2][1]);
                A[mt][1][2] = hrelu2(D[mt][3][0]);
                A[mt][1][3] = hrelu2(D[mt][3][1]);
            }

            // ---- layer 2 (f16 D), bias via C ----
#pragma unroll
            for (int mt = 0; mt < 2; mt++)
#pragma unroll
                for (int nt = 0; nt < 4; nt++) {
                    mmaH(D[mt][nt][0], D[mt][nt][1], A[mt][0], B2h[0][nt],
                         bias2p[nt], bias2p[nt]);
                    mmaH(D[mt][nt][0], D[mt][nt][1], A[mt][1], B2h[1][nt],
                         D[mt][nt][0], D[mt][nt][1]);
                }

            // ---- acc += relu(D2): fold 4 row-groups in f16, then 2 cvt+add ----
#pragma unroll
            for (int nt = 0; nt < 4; nt++) {
                uint32_t s01 = hadd2(hrelu2(D[0][nt][0]), hrelu2(D[0][nt][1]));
                uint32_t s23 = hadd2(hrelu2(D[1][nt][0]), hrelu2(D[1][nt][1]));
                uint32_t s = hadd2(s01, s23);
                float lo, hi;
                unpackH(s, lo, hi);
                accE[nt] += lo;
                accO[nt] += hi;
            }

            i++;
        }
        if (u < u1) { jt++; i = 0; }
    }

    // ---- reduce over the 8 g-groups (t fixed) ----
#pragma unroll
    for (int nt = 0; nt < 4; nt++) {
#pragma unroll
        for (int o = 4; o < 32; o <<= 1) {
            accE[nt] += __shfl_xor_sync(0xffffffffu, accE[nt], o);
            accO[nt] += __shfl_xor_sync(0xffffffffu, accO[nt], o);
        }
    }
    if (lane < 4) {
#pragma unroll
        for (int nt = 0; nt < 4; nt++) {
            g_part[w * HID + 8 * nt + 2 * lane + 0] = accE[nt];
            g_part[w * HID + 8 * nt + 2 * lane + 1] = accO[nt];
        }
    }
}

// ---------------------------------------------------------------------------
// Phase 2: reduce 1184 partials -> s[32]; head MLP -> out[32]
// ---------------------------------------------------------------------------
__global__ void reduce_out(const float* __restrict__ Wp, const float* __restrict__ bp,
                           const float* __restrict__ Wo, const float* __restrict__ bo,
                           float* __restrict__ out) {
    __shared__ float tmp[8][HID];
    __shared__ float s[HID], pvec[HID];
    int tid = threadIdx.x;              // 256
    int k = tid & 31, grp = tid >> 5;
    float lsum = 0.f;
    for (int b = grp; b < NW; b += 8)
        lsum += g_part[b * HID + k];
    tmp[grp][k] = lsum;
    __syncthreads();
    if (tid < HID) {
        float t = 0.f;
#pragma unroll
        for (int gg = 0; gg < 8; gg++) t += tmp[gg][tid];
        s[tid] = t;
    }
    __syncthreads();
    if (tid < HID) {
        float t = bp[tid];
#pragma unroll
        for (int kk = 0; kk < HID; kk++) t = fmaf(s[kk], Wp[kk * HID + tid], t);
        pvec[tid] = fmaxf(t, 0.f);
    }
    __syncthreads();
    if (tid < HID) {
        float t = bo[tid];
#pragma unroll
        for (int kk = 0; kk < HID; kk++) t = fmaf(pvec[kk], Wo[kk * HID + tid], t);
        out[tid] = t;
    }
}

// ---------------------------------------------------------------------------
extern "C" void kernel_launch(void* const* d_in, const int* in_sizes, int n_in,
                              void* d_out, int out_size) {
    const float* x  = (const float*)d_in[0];
    const float* W0 = (const float*)d_in[1];
    const float* b0 = (const float*)d_in[2];
    const float* W1 = (const float*)d_in[3];
    const float* b1 = (const float*)d_in[4];
    const float* W2 = (const float*)d_in[5];
    const float* b2 = (const float*)d_in[6];
    const float* Wp = (const float*)d_in[7];
    const float* bp = (const float*)d_in[8];
    const float* Wo = (const float*)d_in[9];
    const float* bo = (const float*)d_in[10];
    float* out = (float*)d_out;

    precompute_ab<<<(N_PIX * HID * 4 + 255) / 256, 256>>>(x, W0, b0);
    pair_kernel<<<NCTA, 128>>>(W1, b1, W2, b2);
    reduce_out<<<1, 256>>>(Wp, bp, Wo, bo, out);
}